// round 13
// baseline (speedup 1.0000x reference)
#include <cuda_runtime.h>
#include <cuda_bf16.h>
#include <cstdint>

// GradeWiseLinear: block-diagonal 16x16 linear (blocks 1,4,6,4,1) + bias.
// 2,097,152 rows x 16 fp32. 268 MB HBM traffic, pure streaming.
//
// R13: TMA bulk-copy input pipeline. cp.async.bulk (1D, 8 KB tiles) fills a
// 5-stage smem ring paced by mbarriers -> load window no longer limited by
// the register file (R12 showed ptxas splits LDG batches beyond 3). Consumers
// read 32 B/thread from smem (2 conflict-free LDS.128) and run the proven
// R11 half-row compute (role = tid&1, one shfl_xor round, exact blocks),
// storing with st.global.v8.f32.

#define TPB 256
#define STAGES 5
#define TILE_BYTES (TPB * 32)        // 8192 B = 256 chunks of 8 floats
#define FULLMASK 0xffffffffu

static __device__ __forceinline__ uint32_t smem_u32(const void* p) {
    return (uint32_t)__cvta_generic_to_shared(p);
}
static __device__ __forceinline__ void mbar_init(uint32_t mbar, uint32_t cnt) {
    asm volatile("mbarrier.init.shared.b64 [%0], %1;" :: "r"(mbar), "r"(cnt) : "memory");
}
static __device__ __forceinline__ void mbar_expect_tx(uint32_t mbar, uint32_t bytes) {
    asm volatile("mbarrier.arrive.expect_tx.shared.b64 _, [%0], %1;"
                 :: "r"(mbar), "r"(bytes) : "memory");
}
static __device__ __forceinline__ void mbar_arrive(uint32_t mbar) {
    asm volatile("mbarrier.arrive.shared.b64 _, [%0];" :: "r"(mbar) : "memory");
}
static __device__ __forceinline__ void mbar_wait(uint32_t mbar, uint32_t phase) {
    uint32_t done;
    asm volatile(
        "{\n\t.reg .pred p;\n\t"
        "mbarrier.try_wait.parity.acquire.cta.shared::cta.b64 p, [%1], %2;\n\t"
        "selp.b32 %0, 1, 0, p;\n\t}"
        : "=r"(done) : "r"(mbar), "r"(phase) : "memory");
    if (!done) {
        asm volatile(
            "{\n\t.reg .pred P1;\n\t"
            "WL_%=:\n\t"
            "mbarrier.try_wait.parity.acquire.cta.shared::cta.b64 P1, [%0], %1, 0x989680;\n\t"
            "@P1 bra.uni WD_%=;\n\t"
            "bra.uni WL_%=;\n\t"
            "WD_%=:\n\t}"
            :: "r"(mbar), "r"(phase) : "memory");
    }
}
static __device__ __forceinline__ void tma_bulk_g2s(uint32_t dst_smem,
                                                    const void* src, uint32_t bytes,
                                                    uint32_t mbar) {
    asm volatile(
        "cp.async.bulk.shared::cta.global.mbarrier::complete_tx::bytes [%0], [%1], %2, [%3];"
        :: "r"(dst_smem), "l"(src), "r"(bytes), "r"(mbar) : "memory");
}

// per-role smem weight table (48 floats per role):
//  [0..15] Q (4x4: W1/W3)  [16..19] QB  [20..37] H (3x6 of W2)
//  [38..40] HB  [41] ws (w0/w4)  [42] bs (b0/b4)

__global__ void __launch_bounds__(TPB, 3)
gradewise_linear_kernel(const float* __restrict__ x,
                        const float* __restrict__ w0, const float* __restrict__ b0,
                        const float* __restrict__ w1, const float* __restrict__ b1,
                        const float* __restrict__ w2, const float* __restrict__ b2,
                        const float* __restrict__ w3, const float* __restrict__ b3,
                        const float* __restrict__ w4, const float* __restrict__ b4,
                        float* __restrict__ out, int n_chunk, int n_tiles)
{
    __shared__ __align__(16) float sW[2][48];
    __shared__ __align__(128) float sbuf[STAGES][TPB * 8];
    __shared__ __align__(8) uint64_t mb_full[STAGES];
    __shared__ __align__(8) uint64_t mb_empty[STAGES];

    const int tid = threadIdx.x;

    if (tid == 0) {
        sW[0][41] = w0[0];  sW[0][42] = b0[0];
        sW[1][41] = w4[0];  sW[1][42] = b4[0];
#pragma unroll
        for (int i = 0; i < 16; i++) { sW[0][i] = w1[i]; sW[1][i] = w3[i]; }
#pragma unroll
        for (int j = 0; j < 4; j++)  { sW[0][16 + j] = b1[j]; sW[1][16 + j] = b3[j]; }
#pragma unroll
        for (int j = 0; j < 3; j++) {
#pragma unroll
            for (int i = 0; i < 6; i++) {
                sW[0][20 + j * 6 + i] = w2[j * 6 + i];
                sW[1][20 + j * 6 + i] = w2[(3 + j) * 6 + i];
            }
            sW[0][38 + j] = b2[j];
            sW[1][38 + j] = b2[3 + j];
        }
#pragma unroll
        for (int s = 0; s < STAGES; s++) {
            mbar_init(smem_u32(&mb_full[s]), 1);
            mbar_init(smem_u32(&mb_empty[s]), TPB);
        }
    }
    __syncthreads();

    const int role = tid & 1;
    const float* T = sW[role];

    float Q[16], QB[4], H[18], HB[3];
#pragma unroll
    for (int i = 0; i < 16; i++) Q[i] = T[i];
#pragma unroll
    for (int j = 0; j < 4; j++)  QB[j] = T[16 + j];
#pragma unroll
    for (int i = 0; i < 18; i++) H[i] = T[20 + i];
#pragma unroll
    for (int j = 0; j < 3; j++)  HB[j] = T[38 + j];
    const float ws = T[41], bs = T[42];

    // ---- prologue: fill the ring (producer = thread 0) ----
    if (tid == 0) {
#pragma unroll
        for (int i = 0; i < STAGES; i++) {
            int tile = blockIdx.x + i * gridDim.x;
            if (tile < n_tiles) {
                uint32_t mb = smem_u32(&mb_full[i]);
                mbar_expect_tx(mb, TILE_BYTES);
                tma_bulk_g2s(smem_u32(&sbuf[i][0]),
                             x + (size_t)tile * (TPB * 8), TILE_BYTES, mb);
            }
        }
    }

    // ---- steady pipeline ----
    int i = 0;
    for (int tile = blockIdx.x; tile < n_tiles; tile += gridDim.x, i++) {
        const int s = i % STAGES;
        const uint32_t ph = (uint32_t)((i / STAGES) & 1);

        mbar_wait(smem_u32(&mb_full[s]), ph);

        // consume own 32 B chunk (2 conflict-free LDS.128)
        const float4* bp = reinterpret_cast<const float4*>(&sbuf[s][tid * 8]);
        float4 vA = bp[0];
        float4 vB = bp[1];
        float a0 = vA.x, a1 = vA.y, a2 = vA.z, a3 = vA.w;
        float a4 = vB.x, a5 = vB.y, a6 = vB.z, a7 = vB.w;

        // buffer free for refill (release-arrive orders the reads above)
        mbar_arrive(smem_u32(&mb_empty[s]));

        // producer: refill this stage with the tile STAGES ahead
        if (tid == 0) {
            int ntile = tile + STAGES * gridDim.x;
            if (ntile < n_tiles) {
                mbar_wait(smem_u32(&mb_empty[s]), ph);
                uint32_t mb = smem_u32(&mb_full[s]);
                mbar_expect_tx(mb, TILE_BYTES);
                tma_bulk_g2s(smem_u32(&sbuf[s][0]),
                             x + (size_t)ntile * (TPB * 8), TILE_BYTES, mb);
            }
        }

        // ---- R11 compute (role-split half-row) ----
        float s0 = role ? a0 : a5;
        float s1 = role ? a1 : a6;
        float s2 = role ? a2 : a7;
        float p0 = __shfl_xor_sync(FULLMASK, s0, 1);
        float p1 = __shfl_xor_sync(FULLMASK, s1, 1);
        float p2 = __shfl_xor_sync(FULLMASK, s2, 1);

        float vsc = role ? a7 : a0;
        float sc = fmaf(ws, vsc, bs);

        float q0 = role ? a3 : a1;
        float q1 = role ? a4 : a2;
        float q2 = role ? a5 : a3;
        float q3 = role ? a6 : a4;
        float qo[4];
#pragma unroll
        for (int j = 0; j < 4; j++) {
            float acc = QB[j];
            acc = fmaf(Q[j * 4 + 0], q0, acc);
            acc = fmaf(Q[j * 4 + 1], q1, acc);
            acc = fmaf(Q[j * 4 + 2], q2, acc);
            acc = fmaf(Q[j * 4 + 3], q3, acc);
            qo[j] = acc;
        }

        float h0 = role ? p0 : a5;
        float h1 = role ? p1 : a6;
        float h2 = role ? p2 : a7;
        float h3 = role ? a0 : p0;
        float h4 = role ? a1 : p1;
        float h5 = role ? a2 : p2;
        float ho[3];
#pragma unroll
        for (int j = 0; j < 3; j++) {
            float acc = HB[j];
            acc = fmaf(H[j * 6 + 0], h0, acc);
            acc = fmaf(H[j * 6 + 1], h1, acc);
            acc = fmaf(H[j * 6 + 2], h2, acc);
            acc = fmaf(H[j * 6 + 3], h3, acc);
            acc = fmaf(H[j * 6 + 4], h4, acc);
            acc = fmaf(H[j * 6 + 5], h5, acc);
            ho[j] = acc;
        }

        float o0 = role ? ho[0] : sc;
        float o1 = role ? ho[1] : qo[0];
        float o2 = role ? ho[2] : qo[1];
        float o3 = role ? qo[0] : qo[2];
        float o4 = role ? qo[1] : qo[3];
        float o5 = role ? qo[2] : ho[0];
        float o6 = role ? qo[3] : ho[1];
        float o7 = role ? sc    : ho[2];

        float* p = out + (size_t)(tile * TPB + tid) * 8;
        asm volatile(
            "st.global.v8.f32 [%0], {%1,%2,%3,%4,%5,%6,%7,%8};"
            :: "l"(p),
               "f"(o0), "f"(o1), "f"(o2), "f"(o3),
               "f"(o4), "f"(o5), "f"(o6), "f"(o7)
            : "memory");
    }

    // ---- tail: chunks beyond full tiles (block 0; dormant for this shape) ----
    if (blockIdx.x == 0) {
        int idx = n_tiles * TPB + tid;
        bool ok = idx < n_chunk;
        float a0 = 0, a1 = 0, a2 = 0, a3 = 0, a4 = 0, a5 = 0, a6 = 0, a7 = 0;
        if (ok) {
            const float* p = x + (size_t)idx * 8;
            asm volatile(
                "ld.global.v8.f32 {%0,%1,%2,%3,%4,%5,%6,%7}, [%8];"
                : "=f"(a0), "=f"(a1), "=f"(a2), "=f"(a3),
                  "=f"(a4), "=f"(a5), "=f"(a6), "=f"(a7)
                : "l"(p));
        }
        float s0 = role ? a0 : a5;
        float s1 = role ? a1 : a6;
        float s2 = role ? a2 : a7;
        float p0 = __shfl_xor_sync(FULLMASK, s0, 1);
        float p1 = __shfl_xor_sync(FULLMASK, s1, 1);
        float p2 = __shfl_xor_sync(FULLMASK, s2, 1);

        float vsc = role ? a7 : a0;
        float sc = fmaf(ws, vsc, bs);

        float q0 = role ? a3 : a1;
        float q1 = role ? a4 : a2;
        float q2 = role ? a5 : a3;
        float q3 = role ? a6 : a4;
        float qo[4];
#pragma unroll
        for (int j = 0; j < 4; j++) {
            float acc = QB[j];
            acc = fmaf(Q[j * 4 + 0], q0, acc);
            acc = fmaf(Q[j * 4 + 1], q1, acc);
            acc = fmaf(Q[j * 4 + 2], q2, acc);
            acc = fmaf(Q[j * 4 + 3], q3, acc);
            qo[j] = acc;
        }
        float h0 = role ? p0 : a5;
        float h1 = role ? p1 : a6;
        float h2 = role ? p2 : a7;
        float h3 = role ? a0 : p0;
        float h4 = role ? a1 : p1;
        float h5 = role ? a2 : p2;
        float ho[3];
#pragma unroll
        for (int j = 0; j < 3; j++) {
            float acc = HB[j];
            acc = fmaf(H[j * 6 + 0], h0, acc);
            acc = fmaf(H[j * 6 + 1], h1, acc);
            acc = fmaf(H[j * 6 + 2], h2, acc);
            acc = fmaf(H[j * 6 + 3], h3, acc);
            acc = fmaf(H[j * 6 + 4], h4, acc);
            acc = fmaf(H[j * 6 + 5], h5, acc);
            ho[j] = acc;
        }
        if (ok) {
            float o0 = role ? ho[0] : sc;
            float o1 = role ? ho[1] : qo[0];
            float o2 = role ? ho[2] : qo[1];
            float o3 = role ? qo[0] : qo[2];
            float o4 = role ? qo[1] : qo[3];
            float o5 = role ? qo[2] : ho[0];
            float o6 = role ? qo[3] : ho[1];
            float o7 = role ? sc    : ho[2];
            float* p = out + (size_t)idx * 8;
            asm volatile(
                "st.global.v8.f32 [%0], {%1,%2,%3,%4,%5,%6,%7,%8};"
                :: "l"(p),
                   "f"(o0), "f"(o1), "f"(o2), "f"(o3),
                   "f"(o4), "f"(o5), "f"(o6), "f"(o7)
                : "memory");
        }
    }
}

extern "C" void kernel_launch(void* const* d_in, const int* in_sizes, int n_in,
                              void* d_out, int out_size)
{
    const float* x  = (const float*)d_in[0];
    const float* w0 = (const float*)d_in[1];
    const float* b0 = (const float*)d_in[2];
    const float* w1 = (const float*)d_in[3];
    const float* b1 = (const float*)d_in[4];
    const float* w2 = (const float*)d_in[5];
    const float* b2 = (const float*)d_in[6];
    const float* w3 = (const float*)d_in[7];
    const float* b3 = (const float*)d_in[8];
    const float* w4 = (const float*)d_in[9];
    const float* b4 = (const float*)d_in[10];
    float* out = (float*)d_out;

    int n_chunk = in_sizes[0] / 8;       // 8-float half-rows
    int n_tiles = n_chunk / TPB;         // full 8 KB tiles

    int blocks = 456;                    // 3 CTAs/SM x 152 SMs
    if (n_tiles > 0 && blocks > n_tiles) blocks = n_tiles;
    if (n_tiles == 0) blocks = 1;        // tail-only path

    gradewise_linear_kernel<<<blocks, TPB>>>(
        x, w0, b0, w1, b1, w2, b2, w3, b3, w4, b4, out, n_chunk, n_tiles);
}

// round 14
// speedup vs baseline: 1.3690x; 1.3690x over previous
#include <cuda_runtime.h>
#include <cuda_bf16.h>

// GradeWiseLinear: block-diagonal 16x16 linear (blocks 1,4,6,4,1) + bias.
// 2,097,152 rows x 16 fp32. 268 MB HBM traffic, pure streaming.
//
// R14: R11 structure (ld/st.global.v8.f32, half-row per lane, role=lane&1,
// one shfl_xor exchange, exact per-role blocks, ITERS=3) at 4 CTAs/SM:
// hex weights (3x6, padded 3x8 -> 2x LDS.128/row) and all biases read from
// smem at use; only Q(4x4)+ws stay in registers. regs ~80 -> ~60, occupancy
// 3 -> 4 CTAs/SM, in-flight bytes +33% (the validated DRAM% lever).

#define TPB 256
#define ITERS 3
#define FULLMASK 0xffffffffu

__global__ void __launch_bounds__(TPB, 4)
gradewise_linear_kernel(const float* __restrict__ x,
                        const float* __restrict__ w0, const float* __restrict__ b0,
                        const float* __restrict__ w1, const float* __restrict__ b1,
                        const float* __restrict__ w2, const float* __restrict__ b2,
                        const float* __restrict__ w3, const float* __restrict__ b3,
                        const float* __restrict__ w4, const float* __restrict__ b4,
                        float* __restrict__ out, int n_chunk)
{
    // sQ[role][16]: 4x4 block (W1 / W3)
    // sH[role][3][8]: 3x6 half of W2, rows padded to 8 (2x float4 per row)
    // sB[role][8]: [0..3]=quad bias, [4..6]=hex bias, [7]=scalar bias
    // sws[role]: scalar weight (w0 / w4)
    __shared__ __align__(16) float sQ[2][16];
    __shared__ __align__(16) float sH[2][3][8];
    __shared__ __align__(16) float sB[2][8];
    __shared__ float sws[2];

    if (threadIdx.x == 0) {
        sws[0] = w0[0];  sB[0][7] = b0[0];
        sws[1] = w4[0];  sB[1][7] = b4[0];
#pragma unroll
        for (int i = 0; i < 16; i++) { sQ[0][i] = w1[i]; sQ[1][i] = w3[i]; }
#pragma unroll
        for (int j = 0; j < 4; j++)  { sB[0][j] = b1[j]; sB[1][j] = b3[j]; }
#pragma unroll
        for (int j = 0; j < 3; j++) {
#pragma unroll
            for (int i = 0; i < 6; i++) {
                sH[0][j][i] = w2[j * 6 + i];
                sH[1][j][i] = w2[(3 + j) * 6 + i];
            }
            sH[0][j][6] = 0.f; sH[0][j][7] = 0.f;
            sH[1][j][6] = 0.f; sH[1][j][7] = 0.f;
            sB[0][4 + j] = b2[j];
            sB[1][4 + j] = b2[3 + j];
        }
    }
    __syncthreads();

    const int role = threadIdx.x & 1;

    // Registers: only the 4x4 block + scalar weight.
    float Q[16];
#pragma unroll
    for (int i = 0; i < 16; i++) Q[i] = sQ[role][i];
    const float ws = sws[role];
    const float* Brole = sB[role];
    const float (*Hrole)[8] = sH[role];

    const int base = blockIdx.x * (TPB * ITERS) + threadIdx.x;
    const bool full = (blockIdx.x + 1) * (TPB * ITERS) <= n_chunk;

    float a[ITERS][8];
    bool ok[ITERS];

    // ---- phase 1: issue all 256-bit loads (independent, MLP=ITERS) ----
#pragma unroll
    for (int t = 0; t < ITERS; t++) {
        int idx = base + t * TPB;
        ok[t] = full || (idx < n_chunk);
        const float* p = x + (size_t)idx * 8;
        if (ok[t]) {
            asm volatile(
                "ld.global.v8.f32 {%0,%1,%2,%3,%4,%5,%6,%7}, [%8];"
                : "=f"(a[t][0]), "=f"(a[t][1]), "=f"(a[t][2]), "=f"(a[t][3]),
                  "=f"(a[t][4]), "=f"(a[t][5]), "=f"(a[t][6]), "=f"(a[t][7])
                : "l"(p));
        } else {
#pragma unroll
            for (int i = 0; i < 8; i++) a[t][i] = 0.0f;
        }
    }

    // ---- phase 2: exchange + compute + store per sub-iteration ----
#pragma unroll
    for (int t = 0; t < ITERS; t++) {
        // even lane needs odd's a0..a2 (x8..x10); odd needs even's a5..a7.
        float s0 = role ? a[t][0] : a[t][5];
        float s1 = role ? a[t][1] : a[t][6];
        float s2 = role ? a[t][2] : a[t][7];
        float p0 = __shfl_xor_sync(FULLMASK, s0, 1);
        float p1 = __shfl_xor_sync(FULLMASK, s1, 1);
        float p2 = __shfl_xor_sync(FULLMASK, s2, 1);

        // scalar block
        float vsc = role ? a[t][7] : a[t][0];
        float sc = fmaf(ws, vsc, Brole[7]);

        // quad block inputs: role0 x1..x4 = a1..a4; role1 x11..x14 = a3..a6
        float q0 = role ? a[t][3] : a[t][1];
        float q1 = role ? a[t][4] : a[t][2];
        float q2 = role ? a[t][5] : a[t][3];
        float q3 = role ? a[t][6] : a[t][4];
        float qo[4];
#pragma unroll
        for (int j = 0; j < 4; j++) {
            float acc = Brole[j];
            acc = fmaf(Q[j * 4 + 0], q0, acc);
            acc = fmaf(Q[j * 4 + 1], q1, acc);
            acc = fmaf(Q[j * 4 + 2], q2, acc);
            acc = fmaf(Q[j * 4 + 3], q3, acc);
            qo[j] = acc;
        }

        // hex block inputs x5..x10:
        // role0: a5,a6,a7,p0,p1,p2   role1: p0,p1,p2,a0,a1,a2
        float h0 = role ? p0 : a[t][5];
        float h1 = role ? p1 : a[t][6];
        float h2 = role ? p2 : a[t][7];
        float h3 = role ? a[t][0] : p0;
        float h4 = role ? a[t][1] : p1;
        float h5 = role ? a[t][2] : p2;
        float ho[3];
#pragma unroll
        for (int j = 0; j < 3; j++) {
            // weights from smem: 2x LDS.128 (2-address broadcast, no conflict)
            float4 hw0 = *reinterpret_cast<const float4*>(&Hrole[j][0]);
            float4 hw1 = *reinterpret_cast<const float4*>(&Hrole[j][4]);
            float acc = Brole[4 + j];
            acc = fmaf(hw0.x, h0, acc);
            acc = fmaf(hw0.y, h1, acc);
            acc = fmaf(hw0.z, h2, acc);
            acc = fmaf(hw0.w, h3, acc);
            acc = fmaf(hw1.x, h4, acc);
            acc = fmaf(hw1.y, h5, acc);
            ho[j] = acc;
        }

        // output order: role0 {sc,qo0..3,ho0..2}; role1 {ho0..2,qo0..3,sc}
        float o0 = role ? ho[0] : sc;
        float o1 = role ? ho[1] : qo[0];
        float o2 = role ? ho[2] : qo[1];
        float o3 = role ? qo[0] : qo[2];
        float o4 = role ? qo[1] : qo[3];
        float o5 = role ? qo[2] : ho[0];
        float o6 = role ? qo[3] : ho[1];
        float o7 = role ? sc    : ho[2];

        if (ok[t]) {
            int idx = base + t * TPB;
            float* p = out + (size_t)idx * 8;
            asm volatile(
                "st.global.v8.f32 [%0], {%1,%2,%3,%4,%5,%6,%7,%8};"
                :: "l"(p),
                   "f"(o0), "f"(o1), "f"(o2), "f"(o3),
                   "f"(o4), "f"(o5), "f"(o6), "f"(o7)
                : "memory");
        }
    }
}

extern "C" void kernel_launch(void* const* d_in, const int* in_sizes, int n_in,
                              void* d_out, int out_size)
{
    const float* x  = (const float*)d_in[0];
    const float* w0 = (const float*)d_in[1];
    const float* b0 = (const float*)d_in[2];
    const float* w1 = (const float*)d_in[3];
    const float* b1 = (const float*)d_in[4];
    const float* w2 = (const float*)d_in[5];
    const float* b2 = (const float*)d_in[6];
    const float* w3 = (const float*)d_in[7];
    const float* b3 = (const float*)d_in[8];
    const float* w4 = (const float*)d_in[9];
    const float* b4 = (const float*)d_in[10];
    float* out = (float*)d_out;

    int n_chunk = in_sizes[0] / 8;          // 8-float half-rows
    int per_block = TPB * ITERS;
    int blocks = (n_chunk + per_block - 1) / per_block;

    gradewise_linear_kernel<<<blocks, TPB>>>(
        x, w0, b0, w1, b1, w2, b2, w3, b3, w4, b4, out, n_chunk);
}